// round 14
// baseline (speedup 1.0000x reference)
#include <cuda_runtime.h>
#include <cuda_fp16.h>
#include <cstdint>
#include <cstddef>

#define S   2048
#define H   2048
#define NH  16
#define D   128
typedef __half h16;

// ---------------- scratch ----------------------------------------------------
__device__ h16   g_Xhi[(size_t)S * H],  g_Xlo[(size_t)S * H];
__device__ h16   g_wqhi[(size_t)2 * H * H], g_wqlo[(size_t)2 * H * H];
__device__ h16   g_wkhi[(size_t)2 * H * H], g_wklo[(size_t)2 * H * H];
__device__ h16   g_wvhi[(size_t)H * H];
__device__ h16   g_wohi[(size_t)H * H];
__device__ float g_QKraw[(size_t)S * 4 * H];
__device__ h16   g_QWhi[(size_t)NH * S * D], g_QWlo[(size_t)NH * S * D];
__device__ h16   g_KWhi[(size_t)NH * S * D], g_KWlo[(size_t)NH * S * D];
__device__ float g_AK[(size_t)NH * S];
__device__ h16   g_VThi[(size_t)NH * D * S];
__device__ h16   g_AOhi[(size_t)S * H];

// ---------------- helpers -----------------------------------------------------
__device__ __forceinline__ uint32_t smem_u32(const void* p) {
    uint32_t a;
    asm("{ .reg .u64 t; cvta.to.shared.u64 t, %1; cvt.u32.u64 %0, t; }" : "=r"(a) : "l"(p));
    return a;
}
__device__ __forceinline__ void cp16(uint32_t dst, const void* src) {
    asm volatile("cp.async.cg.shared.global [%0], [%1], 16;" :: "r"(dst), "l"(src) : "memory");
}
#define CP_COMMIT() asm volatile("cp.async.commit_group;" ::: "memory")
#define CP_WAIT1()  asm volatile("cp.async.wait_group 1;" ::: "memory")
#define CP_WAIT0()  asm volatile("cp.async.wait_group 0;" ::: "memory")

__device__ __forceinline__ void ldm_x4(uint32_t r[4], uint32_t addr) {
    asm volatile("ldmatrix.sync.aligned.m8n8.x4.shared.b16 {%0,%1,%2,%3}, [%4];"
                 : "=r"(r[0]), "=r"(r[1]), "=r"(r[2]), "=r"(r[3]) : "r"(addr));
}
__device__ __forceinline__ void mma_f32acc(float c[4], const uint32_t a[4],
                                           uint32_t b0, uint32_t b1) {
    asm volatile(
        "mma.sync.aligned.m16n8k16.row.col.f32.f16.f16.f32 "
        "{%0,%1,%2,%3}, {%4,%5,%6,%7}, {%8,%9}, {%0,%1,%2,%3};"
        : "+f"(c[0]), "+f"(c[1]), "+f"(c[2]), "+f"(c[3])
        : "r"(a[0]), "r"(a[1]), "r"(a[2]), "r"(a[3]), "r"(b0), "r"(b1));
}
__device__ __forceinline__ void mma_f16acc(uint32_t c[2], const uint32_t a[4],
                                           uint32_t b0, uint32_t b1) {
    asm volatile(
        "mma.sync.aligned.m16n8k16.row.col.f16.f16.f16.f16 "
        "{%0,%1}, {%2,%3,%4,%5}, {%6,%7}, {%0,%1};"
        : "+r"(c[0]), "+r"(c[1])
        : "r"(a[0]), "r"(a[1]), "r"(a[2]), "r"(a[3]), "r"(b0), "r"(b1));
}
__device__ __forceinline__ void split2h(float x, h16& h, h16& l) {
    h = __float2half_rn(x);
    l = __float2half_rn(x - __half2float(h));
}
__device__ __forceinline__ uint32_t h2pack(float a, float b) {
    __half2 h = __floats2half2_rn(a, b);
    return *reinterpret_cast<uint32_t*>(&h);
}

// ---------------- GEMM (projections), BK=64, 3-stage ring ---------------------
// MODE 0: C = (Ahi+Alo)(Bhi+Blo)^T  3 products, fp32 C.  192KB smem, 1 CTA/SM.
// MODE 1: C = Ahi·Bhi^T             1 product,  fp32 C.   96KB smem, 2 CTA/SM.
// MODE 2: C = Ahi·Bhi^T             1 product,  fp16 VT.  96KB smem, 2 CTA/SM.
#define BK 64
#define MAT_B   16384                        // 128 rows x 64 k x 2B
#define GEMM_SMEM0 (3 * 4 * MAT_B)           // 192KB
#define GEMM_SMEM12 (3 * 2 * MAT_B)          // 96KB

__device__ __forceinline__ uint32_t sw_off(int k16, int row, int half) {
    return (uint32_t)(k16 * 4096 + row * 32 + ((half ^ ((row >> 2) & 1)) << 4));
}

template <int MODE>
__global__ void __launch_bounds__(256, MODE == 0 ? 1 : 2)
gemm_kernel(int M, int N, int K,
            const h16* __restrict__ Ahi, const h16* __restrict__ Alo, int lda,
            const h16* __restrict__ Bhi, const h16* __restrict__ Blo, int ldb,
            const h16* __restrict__ Bhi2, const h16* __restrict__ Blo2, int nsplit,
            float* __restrict__ C, int ldc,
            h16* __restrict__ Cvt)
{
    extern __shared__ char smem[];
    const uint32_t sbase = smem_u32(smem);
    const int tid  = threadIdx.x;
    const int lane = tid & 31;
    const int wid  = tid >> 5;
    const int wm0  = (wid & 1) * 64;
    const int wn0  = (wid >> 1) * 32;

    const uint32_t STG  = (MODE == 0) ? (4 * MAT_B) : (2 * MAT_B);
    const uint32_t BOFF = (MODE == 0) ? (2 * MAT_B) : MAT_B;

    const int m0 = blockIdx.y * 128;
    const int n0 = blockIdx.x * 128;
    int nb0 = n0;
    if (Bhi2 != nullptr && n0 >= nsplit) {
        Bhi = Bhi2; Blo = Blo2; nb0 = n0 - nsplit;
    }

    // per matrix: 1024 16B-chunks; 256 threads x 4 chunks
    auto load_stage = [&](int kt, int stg) {
        const int k0 = kt * BK;
        const uint32_t sb = sbase + stg * STG;
#pragma unroll
        for (int j = 0; j < 4; j++) {
            const int c    = tid + j * 256;       // 0..1023
            const int k16  = c >> 8;              // 0..3
            const int row  = (c & 255) >> 1;      // 0..127
            const int half = c & 1;
            const int kel  = k0 + k16 * 16 + half * 8;
            const uint32_t so = sw_off(k16, row, half);
            cp16(sb + so,             Ahi + (size_t)(m0 + row) * lda + kel);
            if (MODE == 0)
                cp16(sb + MAT_B + so, Alo + (size_t)(m0 + row) * lda + kel);
            cp16(sb + BOFF + so,      Bhi + (size_t)(nb0 + row) * ldb + kel);
            if (MODE == 0)
                cp16(sb + BOFF + MAT_B + so, Blo + (size_t)(nb0 + row) * ldb + kel);
        }
    };

    float acc[4][4][4];
    uint32_t cacc[4][4][2];
#pragma unroll
    for (int i = 0; i < 4; i++)
#pragma unroll
        for (int j = 0; j < 4; j++) {
#pragma unroll
            for (int r = 0; r < 4; r++) acc[i][j][r] = 0.f;
            cacc[i][j][0] = 0u; cacc[i][j][1] = 0u;
        }

    auto compute_stage = [&](uint32_t sb) {
#pragma unroll
        for (int k16 = 0; k16 < 4; k16++) {
            uint32_t ah[4][4], al[4][4];
#pragma unroll
            for (int mt = 0; mt < 4; mt++) {
                const int row = wm0 + mt * 16 + (lane & 15);
                const uint32_t off = sw_off(k16, row, lane >> 4);
                ldm_x4(ah[mt], sb + off);
                if (MODE == 0) ldm_x4(al[mt], sb + MAT_B + off);
            }
            uint32_t bh[2][4], bl[2][4];
#pragma unroll
            for (int g = 0; g < 2; g++) {
                const int row = wn0 + g * 16 + (lane & 15);
                const uint32_t off = sw_off(k16, row, lane >> 4);
                ldm_x4(bh[g], sb + BOFF + off);
                if (MODE == 0) ldm_x4(bl[g], sb + BOFF + MAT_B + off);
            }
#pragma unroll
            for (int mt = 0; mt < 4; mt++) {
#pragma unroll
                for (int nt = 0; nt < 4; nt++) {
                    const int g = nt >> 1;
                    const int p = nt & 1;
                    const uint32_t b0h = bh[g][p], b1h = bh[g][p + 2];
                    mma_f32acc(acc[mt][nt], ah[mt], b0h, b1h);
                    if (MODE == 0) {
                        mma_f16acc(cacc[mt][nt], ah[mt], bl[g][p], bl[g][p + 2]);
                        mma_f16acc(cacc[mt][nt], al[mt], b0h, b1h);
                    }
                }
            }
        }
    };

    // 3-stage ring (all modes). Pending at top of iter kt: {L(kt), L(kt+1)}.
    // Writer of stage (kt+2)%3 overwrites buffer last read at iter kt-1,
    // protected by the top-of-iter-kt barrier -> no trailing barrier.
    const int nk = K / BK;
    load_stage(0, 0); CP_COMMIT();
    load_stage(1, 1); CP_COMMIT();
    for (int kt = 0; kt < nk; kt++) {
        if (kt + 1 < nk) { CP_WAIT1(); } else { CP_WAIT0(); }
        __syncthreads();
        compute_stage(sbase + (uint32_t)(kt % 3) * STG);
        if (kt + 2 < nk) { load_stage(kt + 2, (kt + 2) % 3); CP_COMMIT(); }
    }

    if (MODE == 2) {
        __syncthreads();   // stage reads done before reusing smem for epilogue
        h16* st = reinterpret_cast<h16*>(smem);
        const int rr = wm0 + (lane >> 2);
        const int cc = wn0 + (lane & 3) * 2;
#pragma unroll
        for (int mt = 0; mt < 4; mt++) {
#pragma unroll
            for (int nt = 0; nt < 4; nt++) {
                const int r = rr + mt * 16;
                const int c = cc + nt * 8;
                st[r * 130 + c]           = __float2half_rn(acc[mt][nt][0]);
                st[r * 130 + c + 1]       = __float2half_rn(acc[mt][nt][1]);
                st[(r + 8) * 130 + c]     = __float2half_rn(acc[mt][nt][2]);
                st[(r + 8) * 130 + c + 1] = __float2half_rn(acc[mt][nt][3]);
            }
        }
        __syncthreads();
        const int d  = tid & 127;
        const int sh = tid >> 7;
        h16* dst = Cvt + (size_t)(n0 + d) * S + m0 + sh * 64;
#pragma unroll
        for (int i = 0; i < 64; i += 8) {
            __align__(16) h16 tmp[8];
#pragma unroll
            for (int u = 0; u < 8; u++) tmp[u] = st[(sh * 64 + i + u) * 130 + d];
            *reinterpret_cast<float4*>(dst + i) = *reinterpret_cast<float4*>(tmp);
        }
    } else {
        const int rbase = m0 + wm0 + (lane >> 2);
        const int cbase = n0 + wn0 + (lane & 3) * 2;
#pragma unroll
        for (int mt = 0; mt < 4; mt++) {
#pragma unroll
            for (int nt = 0; nt < 4; nt++) {
                const int row = rbase + mt * 16;
                const int col = cbase + nt * 8;
                float v0 = acc[mt][nt][0], v1 = acc[mt][nt][1];
                float v2 = acc[mt][nt][2], v3 = acc[mt][nt][3];
                if (MODE == 0) {
                    float2 c01 = __half22float2(*reinterpret_cast<__half2*>(&cacc[mt][nt][0]));
                    float2 c23 = __half22float2(*reinterpret_cast<__half2*>(&cacc[mt][nt][1]));
                    v0 += c01.x; v1 += c01.y; v2 += c23.x; v3 += c23.y;
                }
                *reinterpret_cast<float2*>(C + (size_t)row * ldc + col)       = make_float2(v0, v1);
                *reinterpret_cast<float2*>(C + (size_t)(row + 8) * ldc + col) = make_float2(v2, v3);
            }
        }
    }
}

// ---------------- flash attention: scores + softmax + PV fused ----------------
#define FL_STG   49152
#define FL_SMEM  (3 * FL_STG)
#define FL_KW_HI 0
#define FL_KW_LO 16384
#define FL_VT_HI 32768

__global__ void __launch_bounds__(256, 1)
flash_kernel(const h16* __restrict__ QWhi, const h16* __restrict__ QWlo,
             const h16* __restrict__ KWhi, const h16* __restrict__ KWlo,
             const h16* __restrict__ VThi,
             const float* __restrict__ AK,
             h16* __restrict__ AOhi)
{
    extern __shared__ char smem[];
    const uint32_t sbase = smem_u32(smem);
    const int tid = threadIdx.x, lane = tid & 31, wid = tid >> 5;
    const int m0 = blockIdx.x * 128;
    const int h  = blockIdx.y;

    const h16* Qh = QWhi + ((size_t)h * S + m0) * D;
    const h16* Ql = QWlo + ((size_t)h * S + m0) * D;
    const h16* Kh = KWhi + (size_t)h * S * D;
    const h16* Kl = KWlo + (size_t)h * S * D;
    const h16* Vh = VThi + (size_t)h * D * S;
    const float* ak = AK + (size_t)h * S;

#pragma unroll
    for (int j = 0; j < 8; j++) {
        int c = tid + j * 256;
        int k16 = c >> 8, row = (c & 255) >> 1, half = c & 1;
        uint32_t so = (uint32_t)(k16 * 4096 + row * 32 + ((half ^ ((row >> 2) & 1)) << 4));
        const size_t goff = (size_t)row * D + k16 * 16 + half * 8;
        cp16(sbase + so,         Qh + goff);
        cp16(sbase + 32768 + so, Ql + goff);
    }
    CP_COMMIT();
    CP_WAIT0();
    __syncthreads();

    uint32_t a_hi[8][4], a_lo[8][4];
    {
        const int arow = wid * 16 + (lane & 15);
        const uint32_t sw = (uint32_t)(((lane >> 4) ^ ((arow >> 2) & 1)) << 4);
#pragma unroll
        for (int kk = 0; kk < 8; kk++) {
            const uint32_t off = kk * 4096 + arow * 32 + sw;
            ldm_x4(a_hi[kk], sbase + off);
            ldm_x4(a_lo[kk], sbase + 32768 + off);
        }
    }
    __syncthreads();

    auto load_stage = [&](int kt, int stg) {
        const uint32_t sb = sbase + (uint32_t)stg * FL_STG;
        const int key0 = kt * 64;
#pragma unroll
        for (int j = 0; j < 4; j++) {
            int c = tid + j * 256;
            int k16 = c >> 7, row = (c & 127) >> 1, half = c & 1;
            uint32_t so = (uint32_t)(k16 * 2048 + row * 32 + ((half ^ ((row >> 2) & 1)) << 4));
            size_t goff = (size_t)(key0 + row) * D + k16 * 16 + half * 8;
            cp16(sb + FL_KW_HI + so, Kh + goff);
            cp16(sb + FL_KW_LO + so, Kl + goff);
        }
#pragma unroll
        for (int j = 0; j < 4; j++) {
            int c = tid + j * 256;
            int k16 = c >> 8, row = (c & 255) >> 1, half = c & 1;
            uint32_t so = (uint32_t)(k16 * 4096 + row * 32 + ((half ^ ((row >> 2) & 1)) << 4));
            size_t goff = (size_t)row * S + key0 + k16 * 16 + half * 8;
            cp16(sb + FL_VT_HI + so, Vh + goff);
        }
    };

    float acc_o[16][4];
#pragma unroll
    for (int i = 0; i < 16; i++)
#pragma unroll
        for (int r = 0; r < 4; r++) acc_o[i][r] = 0.f;
    float M0 = -1e30f, M1 = -1e30f, L0 = 0.f, L1 = 0.f;

    load_stage(0, 0); CP_COMMIT();
    load_stage(1, 1); CP_COMMIT();

    for (int kt = 0; kt < 32; kt++) {
        CP_WAIT1();
        __syncthreads();
        const uint32_t sb = sbase + (uint32_t)(kt % 3) * FL_STG;

        float sacc[8][4];
#pragma unroll
        for (int t = 0; t < 8; t++)
#pragma unroll
            for (int r = 0; r < 4; r++) sacc[t][r] = 0.f;
#pragma unroll
        for (int kk = 0; kk < 8; kk++) {
#pragma unroll
            for (int g = 0; g < 4; g++) {
                const int brow = g * 16 + (lane & 15);
                const uint32_t off = kk * 2048 + brow * 32
                                   + (((lane >> 4) ^ ((brow >> 2) & 1)) << 4);
                uint32_t bh[4], bl[4];
                ldm_x4(bh, sb + FL_KW_HI + off);
                ldm_x4(bl, sb + FL_KW_LO + off);
#pragma unroll
                for (int p = 0; p < 2; p++) {
                    const int t = g * 2 + p;
                    mma_f32acc(sacc[t], a_hi[kk], bh[p], bh[p + 2]);
                    mma_f32acc(sacc[t], a_hi[kk], bl[p], bl[p + 2]);
                    mma_f32acc(sacc[t], a_lo[kk], bh[p], bh[p + 2]);
                }
            }
        }
        const int keyc = kt * 64 + (lane & 3) * 2;
#pragma unroll
        for (int t = 0; t < 8; t++) {
            const float akA = __ldg(ak + keyc + t * 8);
            const float akB = __ldg(ak + keyc + t * 8 + 1);
            sacc[t][0] += akA; sacc[t][1] += akB;
            sacc[t][2] += akA; sacc[t][3] += akB;
        }
        float mt0 = -1e30f, mt1 = -1e30f;
#pragma unroll
        for (int t = 0; t < 8; t++) {
            mt0 = fmaxf(mt0, fmaxf(sacc[t][0], sacc[t][1]));
            mt1 = fmaxf(mt1, fmaxf(sacc[t][2], sacc[t][3]));
        }
        mt0 = fmaxf(mt0, __shfl_xor_sync(0xffffffffu, mt0, 1));
        mt0 = fmaxf(mt0, __shfl_xor_sync(0xffffffffu, mt0, 2));
        mt1 = fmaxf(mt1, __shfl_xor_sync(0xffffffffu, mt1, 1));
        mt1 = fmaxf(mt1, __shfl_xor_sync(0xffffffffu, mt1, 2));
        const float Mn0 = fmaxf(M0, mt0), Mn1 = fmaxf(M1, mt1);
        const float al0 = __expf(M0 - Mn0), al1 = __expf(M1 - Mn1);
        M0 = Mn0; M1 = Mn1;

        uint32_t pa[4][4];
        float s0 = 0.f, s1 = 0.f;
#pragma unroll
        for (int q = 0; q < 4; q++) {
#pragma unroll
            for (int pp = 0; pp < 2; pp++) {
                const int t = q * 2 + pp;
                const float p00 = __expf(sacc[t][0] - Mn0);
                const float p01 = __expf(sacc[t][1] - Mn0);
                const float p10 = __expf(sacc[t][2] - Mn1);
                const float p11 = __expf(sacc[t][3] - Mn1);
                s0 += p00 + p01; s1 += p10 + p11;
                pa[q][pp * 2]     = h2pack(p00, p01);
                pa[q][pp * 2 + 1] = h2pack(p10, p11);
            }
        }
        L0 = L0 * al0 + s0; L1 = L1 * al1 + s1;
#pragma unroll
        for (int nt = 0; nt < 16; nt++) {
            acc_o[nt][0] *= al0; acc_o[nt][1] *= al0;
            acc_o[nt][2] *= al1; acc_o[nt][3] *= al1;
        }
#pragma unroll
        for (int q = 0; q < 4; q++) {
#pragma unroll
            for (int dg = 0; dg < 8; dg++) {
                const int vrow = dg * 16 + (lane & 15);
                const uint32_t off = q * 4096 + vrow * 32
                                   + (((lane >> 4) ^ ((vrow >> 2) & 1)) << 4);
                uint32_t vh[4];
                ldm_x4(vh, sb + FL_VT_HI + off);
#pragma unroll
                for (int p = 0; p < 2; p++) {
                    const int nt = dg * 2 + p;
                    mma_f32acc(acc_o[nt], pa[q], vh[p], vh[p + 2]);
                }
            }
        }
        if (kt + 2 < 32) load_stage(kt + 2, (kt + 2) % 3);
        CP_COMMIT();
    }

    L0 += __shfl_xor_sync(0xffffffffu, L0, 1);
    L0 += __shfl_xor_sync(0xffffffffu, L0, 2);
    L1 += __shfl_xor_sync(0xffffffffu, L1, 1);
    L1 += __shfl_xor_sync(0xffffffffu, L1, 2);
    const float i0 = 1.f / L0, i1 = 1.f / L1;
    const int r0 = m0 + wid * 16 + (lane >> 2);
    const int cb = (lane & 3) * 2;
#pragma unroll
    for (int nt = 0; nt < 16; nt++) {
        const int d = nt * 8 + cb;
        __half2 hp0 = __floats2half2_rn(acc_o[nt][0] * i0, acc_o[nt][1] * i0);
        __half2 hp1 = __floats2half2_rn(acc_o[nt][2] * i1, acc_o[nt][3] * i1);
        *reinterpret_cast<__half2*>(AOhi + (size_t)r0 * H + h * D + d)       = hp0;
        *reinterpret_cast<__half2*>(AOhi + (size_t)(r0 + 8) * H + h * D + d) = hp1;
    }
}

// ---------------- unified prep: all splits + casts in one launch --------------
#define PREP_UNITS 1835008
__global__ void prep_kernel(const float* __restrict__ X,
                            const float* __restrict__ wq, const float* __restrict__ wk,
                            const float* __restrict__ wv, const float* __restrict__ wo,
                            h16* __restrict__ Xhi, h16* __restrict__ Xlo,
                            h16* __restrict__ wqhi, h16* __restrict__ wqlo,
                            h16* __restrict__ wkhi, h16* __restrict__ wklo,
                            h16* __restrict__ wvhi, h16* __restrict__ wohi)
{
    int i = blockIdx.x * blockDim.x + threadIdx.x;
    if (i >= PREP_UNITS) return;
    const float* src;
    h16 *hi, *lo = nullptr;
    int j;
    if (i < 262144)       { src = X;  hi = Xhi;  lo = Xlo;  j = i; }
    else if (i < 786432)  { src = wq; hi = wqhi; lo = wqlo; j = i - 262144; }
    else if (i < 1310720) { src = wk; hi = wkhi; lo = wklo; j = i - 786432; }
    else if (i < 1572864) { src = wv; hi = wvhi;            j = i - 1310720; }
    else                  { src = wo; hi = wohi;            j = i - 1572864; }

    const float4* xp = reinterpret_cast<const float4*>(src) + (size_t)j * 4;
    float4 v0 = xp[0], v1 = xp[1], v2 = xp[2], v3 = xp[3];
    float vv[16] = {v0.x, v0.y, v0.z, v0.w, v1.x, v1.y, v1.z, v1.w,
                    v2.x, v2.y, v2.z, v2.w, v3.x, v3.y, v3.z, v3.w};
    __align__(16) h16 hb[16];
    if (lo != nullptr) {
        __align__(16) h16 lb[16];
#pragma unroll
        for (int u = 0; u < 16; u++) split2h(vv[u], hb[u], lb[u]);
        float4* lp = reinterpret_cast<float4*>(lo) + (size_t)j * 2;
        lp[0] = *reinterpret_cast<float4*>(lb);
        lp[1] = *reinterpret_cast<float4*>(lb + 8);
    } else {
#pragma unroll
        for (int u = 0; u < 16; u++) hb[u] = __float2half_rn(vv[u]);
    }
    float4* hp = reinterpret_cast<float4*>(hi) + (size_t)j * 2;
    hp[0] = *reinterpret_cast<float4*>(hb);
    hp[1] = *reinterpret_cast<float4*>(hb + 8);
}

// ---------------- softplus + var-weight + RoPE (fast-math) -------------------
__global__ void __launch_bounds__(256)
transform_kernel(const float* __restrict__ QKraw,
                 const float* __restrict__ cosT, const float* __restrict__ sinT,
                 h16* __restrict__ QWhi, h16* __restrict__ QWlo,
                 h16* __restrict__ KWhi, h16* __restrict__ KWlo,
                 float* __restrict__ AK)
{
    const int item = blockIdx.x * 8 + (threadIdx.x >> 5);
    const int lane = threadIdx.x & 31;
    const int s = item & (S - 1);
    const int h = (item >> 11) & (NH - 1);
    const int z = item >> 15;
    h16* Whi = z ? KWhi : QWhi;
    h16* Wlo = z ? KWlo : QWlo;

    const float* base = QKraw + (size_t)s * (4 * H) + z * (2 * H) + h * (2 * D);
    float w[4], sg[4];
#pragma unroll
    for (int j = 0; j < 4; j++) {
        const int d = lane + 32 * j;
        const float mu = base[d];
        const float sr = base[D + d];
        const float sp = (sr > 8.f) ? sr : __logf(1.f + __expf(sr));
        sg[j] = sp + 1e-4f;
        w[j] = mu * rsqrtf(sg[j]);
    }
    float wr[4];
#pragma unroll
    for (int j = 0; j < 4; j++) {
        const int d = lane + 32 * j;
        const float rh = (j < 2) ? -w[j + 2] : w[j - 2];
        wr[j] = w[j] * cosT[(size_t)s * D + d] + rh * sinT[(size_t)s * D + d];
        h16 hh, ll;
        split2h(wr[j], hh, ll);
        const size_t o = ((size_t)h * S + s) * D + d;
        Whi[o] = hh;  Wlo[o] = ll;
    }
    if (z) {
        float red = 0.f;
#pragma unroll
        for (int j = 0; j < 4; j++) red += wr[j] * wr[j] + __logf(sg[j]);
#pragma unroll
        for (int o = 16; o > 0; o >>= 1) red += __shfl_xor_sync(0xffffffffu, red, o);
        if (lane == 0) AK[(size_t)h * S + s] = -0.5f * red;
    }
}

// ---------------- launch ------------------------------------------------------
extern "C" void kernel_launch(void* const* d_in, const int* in_sizes, int n_in,
                              void* d_out, int out_size)
{
    const float* X    = (const float*)d_in[0];
    const float* cosT = (const float*)d_in[1];
    const float* sinT = (const float*)d_in[2];
    const float* w_q  = (const float*)d_in[3];
    const float* w_k  = (const float*)d_in[4];
    const float* w_v  = (const float*)d_in[5];
    const float* w_o  = (const float*)d_in[6];
    float* out = (float*)d_out;

    h16 *Xhi, *Xlo, *wqhi, *wqlo, *wkhi, *wklo, *wvhi, *wohi;
    float *QKraw, *AK;
    h16 *QWhi, *QWlo, *KWhi, *KWlo, *VThi, *AOhi;
    cudaGetSymbolAddress((void**)&Xhi, g_Xhi);   cudaGetSymbolAddress((void**)&Xlo, g_Xlo);
    cudaGetSymbolAddress((void**)&wqhi, g_wqhi); cudaGetSymbolAddress((void**)&wqlo, g_wqlo);
    cudaGetSymbolAddress((void**)&wkhi, g_wkhi); cudaGetSymbolAddress((void**)&wklo, g_wklo);
    cudaGetSymbolAddress((void**)&wvhi, g_wvhi); cudaGetSymbolAddress((void**)&wohi, g_wohi);
    cudaGetSymbolAddress((void**)&QKraw, g_QKraw);
    cudaGetSymbolAddress((void**)&QWhi, g_QWhi); cudaGetSymbolAddress((void**)&QWlo, g_QWlo);
    cudaGetSymbolAddress((void**)&KWhi, g_KWhi); cudaGetSymbolAddress((void**)&KWlo, g_KWlo);
    cudaGetSymbolAddress((void**)&AK, g_AK);
    cudaGetSymbolAddress((void**)&VThi, g_VThi);
    cudaGetSymbolAddress((void**)&AOhi, g_AOhi);

    cudaFuncSetAttribute(gemm_kernel<0>,
                         cudaFuncAttributeMaxDynamicSharedMemorySize, GEMM_SMEM0);
    cudaFuncSetAttribute(gemm_kernel<1>,
                         cudaFuncAttributeMaxDynamicSharedMemorySize, GEMM_SMEM12);
    cudaFuncSetAttribute(gemm_kernel<2>,
                         cudaFuncAttributeMaxDynamicSharedMemorySize, GEMM_SMEM12);
    cudaFuncSetAttribute(flash_kernel,
                         cudaFuncAttributeMaxDynamicSharedMemorySize, FL_SMEM);

    prep_kernel<<<(PREP_UNITS + 255) / 256, 256>>>(
        X, w_q, w_k, w_v, w_o,
        Xhi, Xlo, wqhi, wqlo, wkhi, wklo, wvhi, wohi);

    gemm_kernel<0><<<dim3(8192 / 128, S / 128, 1), 256, GEMM_SMEM0>>>(
        S, 8192, H, Xhi, Xlo, H, wqhi, wqlo, H,
        wkhi, wklo, 4096, QKraw, 8192, nullptr);

    gemm_kernel<2><<<dim3(H / 128, S / 128, 1), 256, GEMM_SMEM12>>>(
        S, H, H, Xhi, nullptr, H, wvhi, nullptr, H,
        nullptr, nullptr, 1 << 30, nullptr, 0, VThi);

    transform_kernel<<<(S * NH * 2) / 8, 256>>>(QKraw, cosT, sinT,
                                                QWhi, QWlo, KWhi, KWlo, AK);

    flash_kernel<<<dim3(S / 128, NH), 256, FL_SMEM>>>(
        QWhi, QWlo, KWhi, KWlo, VThi, AK, AOhi);

    gemm_kernel<1><<<dim3(H / 128, S / 128, 1), 256, GEMM_SMEM12>>>(
        S, H, H, AOhi, nullptr, H, wohi, nullptr, H,
        nullptr, nullptr, 1 << 30, out, H, nullptr);
}

// round 15
// speedup vs baseline: 1.0302x; 1.0302x over previous
#include <cuda_runtime.h>
#include <cuda_fp16.h>
#include <cstdint>
#include <cstddef>

#define S   2048
#define H   2048
#define NH  16
#define D   128
typedef __half h16;

// ---------------- scratch ----------------------------------------------------
__device__ h16   g_Xhi[(size_t)S * H],  g_Xlo[(size_t)S * H];
__device__ h16   g_wqhi[(size_t)2 * H * H], g_wqlo[(size_t)2 * H * H];
__device__ h16   g_wkhi[(size_t)2 * H * H], g_wklo[(size_t)2 * H * H];
__device__ h16   g_wvhi[(size_t)H * H];
__device__ h16   g_wohi[(size_t)H * H];
__device__ float g_QKraw[(size_t)S * 4 * H];
__device__ h16   g_QWhi[(size_t)NH * S * D], g_QWlo[(size_t)NH * S * D];
__device__ h16   g_KWhi[(size_t)NH * S * D], g_KWlo[(size_t)NH * S * D];
__device__ float g_AK[(size_t)NH * S];
__device__ h16   g_VThi[(size_t)NH * D * S];
__device__ h16   g_AOhi[(size_t)S * H];

// ---------------- helpers -----------------------------------------------------
__device__ __forceinline__ uint32_t smem_u32(const void* p) {
    uint32_t a;
    asm("{ .reg .u64 t; cvta.to.shared.u64 t, %1; cvt.u32.u64 %0, t; }" : "=r"(a) : "l"(p));
    return a;
}
__device__ __forceinline__ void cp16(uint32_t dst, const void* src) {
    asm volatile("cp.async.cg.shared.global [%0], [%1], 16;" :: "r"(dst), "l"(src) : "memory");
}
#define CP_COMMIT() asm volatile("cp.async.commit_group;" ::: "memory")
#define CP_WAIT2()  asm volatile("cp.async.wait_group 2;" ::: "memory")
#define CP_WAIT1()  asm volatile("cp.async.wait_group 1;" ::: "memory")
#define CP_WAIT0()  asm volatile("cp.async.wait_group 0;" ::: "memory")

__device__ __forceinline__ void ldm_x4(uint32_t r[4], uint32_t addr) {
    asm volatile("ldmatrix.sync.aligned.m8n8.x4.shared.b16 {%0,%1,%2,%3}, [%4];"
                 : "=r"(r[0]), "=r"(r[1]), "=r"(r[2]), "=r"(r[3]) : "r"(addr));
}
__device__ __forceinline__ void mma_f32acc(float c[4], const uint32_t a[4],
                                           uint32_t b0, uint32_t b1) {
    asm volatile(
        "mma.sync.aligned.m16n8k16.row.col.f32.f16.f16.f32 "
        "{%0,%1,%2,%3}, {%4,%5,%6,%7}, {%8,%9}, {%0,%1,%2,%3};"
        : "+f"(c[0]), "+f"(c[1]), "+f"(c[2]), "+f"(c[3])
        : "r"(a[0]), "r"(a[1]), "r"(a[2]), "r"(a[3]), "r"(b0), "r"(b1));
}
__device__ __forceinline__ void mma_f16acc(uint32_t c[2], const uint32_t a[4],
                                           uint32_t b0, uint32_t b1) {
    asm volatile(
        "mma.sync.aligned.m16n8k16.row.col.f16.f16.f16.f16 "
        "{%0,%1}, {%2,%3,%4,%5}, {%6,%7}, {%0,%1};"
        : "+r"(c[0]), "+r"(c[1])
        : "r"(a[0]), "r"(a[1]), "r"(a[2]), "r"(a[3]), "r"(b0), "r"(b1));
}
__device__ __forceinline__ void split2h(float x, h16& h, h16& l) {
    h = __float2half_rn(x);
    l = __float2half_rn(x - __half2float(h));
}
__device__ __forceinline__ uint32_t h2pack(float a, float b) {
    __half2 h = __floats2half2_rn(a, b);
    return *reinterpret_cast<uint32_t*>(&h);
}

// ---------------- GEMM (projections), BK=32 ------------------------------------
// MODE 0: C = (Ahi+Alo)(Bhi+Blo)^T  3 products, fp32 C.  4-stage, 128KB, 1 CTA/SM.
// MODE 1: C = Ahi·Bhi^T             1 product,  fp32 C.  3-stage,  48KB, 2 CTA/SM.
// MODE 2: C = Ahi·Bhi^T             1 product,  fp16 VT. 3-stage,  48KB, 2 CTA/SM.
#define BK 32
#define MAT_B   8192
#define GEMM_SMEM0  (4 * 4 * MAT_B)   // 128KB
#define GEMM_SMEM12 (3 * 2 * MAT_B)   // 48KB (>= 33280B MODE2 epilogue)

__device__ __forceinline__ uint32_t sw_off(int k16, int row, int half) {
    return (uint32_t)(k16 * 4096 + row * 32 + ((half ^ ((row >> 2) & 1)) << 4));
}

template <int MODE>
__global__ void __launch_bounds__(256, MODE == 0 ? 1 : 2)
gemm_kernel(int M, int N, int K,
            const h16* __restrict__ Ahi, const h16* __restrict__ Alo, int lda,
            const h16* __restrict__ Bhi, const h16* __restrict__ Blo, int ldb,
            const h16* __restrict__ Bhi2, const h16* __restrict__ Blo2, int nsplit,
            float* __restrict__ C, int ldc,
            h16* __restrict__ Cvt)
{
    extern __shared__ char smem[];
    const uint32_t sbase = smem_u32(smem);
    const int tid  = threadIdx.x;
    const int lane = tid & 31;
    const int wid  = tid >> 5;
    const int wm0  = (wid & 1) * 64;
    const int wn0  = (wid >> 1) * 32;

    const uint32_t STG  = (MODE == 0) ? (4 * MAT_B) : (2 * MAT_B);
    const uint32_t BOFF = (MODE == 0) ? (2 * MAT_B) : MAT_B;

    const int m0 = blockIdx.y * 128;
    const int n0 = blockIdx.x * 128;
    int nb0 = n0;
    if (Bhi2 != nullptr && n0 >= nsplit) {
        Bhi = Bhi2; Blo = Blo2; nb0 = n0 - nsplit;
    }

    auto load_stage = [&](int kt, int stg) {
        const int k0 = kt * BK;
        const uint32_t sb = sbase + stg * STG;
#pragma unroll
        for (int j = 0; j < 2; j++) {
            const int c    = tid + j * 256;
            const int k16  = c >> 8;
            const int row  = (c & 255) >> 1;
            const int half = c & 1;
            const int kel  = k0 + k16 * 16 + half * 8;
            const uint32_t so = sw_off(k16, row, half);
            cp16(sb + so,             Ahi + (size_t)(m0 + row) * lda + kel);
            if (MODE == 0)
                cp16(sb + MAT_B + so, Alo + (size_t)(m0 + row) * lda + kel);
            cp16(sb + BOFF + so,      Bhi + (size_t)(nb0 + row) * ldb + kel);
            if (MODE == 0)
                cp16(sb + BOFF + MAT_B + so, Blo + (size_t)(nb0 + row) * ldb + kel);
        }
    };

    float acc[4][4][4];
    uint32_t cacc[4][4][2];
#pragma unroll
    for (int i = 0; i < 4; i++)
#pragma unroll
        for (int j = 0; j < 4; j++) {
#pragma unroll
            for (int r = 0; r < 4; r++) acc[i][j][r] = 0.f;
            cacc[i][j][0] = 0u; cacc[i][j][1] = 0u;
        }

    auto compute_stage = [&](uint32_t sb) {
#pragma unroll
        for (int k16 = 0; k16 < 2; k16++) {
            uint32_t ah[4][4], al[4][4];
#pragma unroll
            for (int mt = 0; mt < 4; mt++) {
                const int row = wm0 + mt * 16 + (lane & 15);
                const uint32_t off = sw_off(k16, row, lane >> 4);
                ldm_x4(ah[mt], sb + off);
                if (MODE == 0) ldm_x4(al[mt], sb + MAT_B + off);
            }
            uint32_t bh[2][4], bl[2][4];
#pragma unroll
            for (int g = 0; g < 2; g++) {
                const int row = wn0 + g * 16 + (lane & 15);
                const uint32_t off = sw_off(k16, row, lane >> 4);
                ldm_x4(bh[g], sb + BOFF + off);
                if (MODE == 0) ldm_x4(bl[g], sb + BOFF + MAT_B + off);
            }
#pragma unroll
            for (int mt = 0; mt < 4; mt++) {
#pragma unroll
                for (int nt = 0; nt < 4; nt++) {
                    const int g = nt >> 1;
                    const int p = nt & 1;
                    const uint32_t b0h = bh[g][p], b1h = bh[g][p + 2];
                    mma_f32acc(acc[mt][nt], ah[mt], b0h, b1h);
                    if (MODE == 0) {
                        mma_f16acc(cacc[mt][nt], ah[mt], bl[g][p], bl[g][p + 2]);
                        mma_f16acc(cacc[mt][nt], al[mt], b0h, b1h);
                    }
                }
            }
        }
    };

    const int nk = K / BK;
    if (MODE == 0) {
        // 4-stage, lookahead-2, no trailing barrier (R13-proven optimum)
        load_stage(0, 0); CP_COMMIT();
        load_stage(1, 1); CP_COMMIT();
        for (int kt = 0; kt < nk; kt++) {
            if (kt + 2 < nk) load_stage(kt + 2, (kt + 2) & 3);
            CP_COMMIT();
            CP_WAIT2();
            __syncthreads();
            compute_stage(sbase + (kt & 3) * STG);
        }
    } else {
        // 3-stage ring: pending at top of iter kt = {L(kt), L(kt+1)} -> wait 1.
        // Writer of stage (kt+2)%3 overwrites buffer last read at iter kt-1,
        // protected by the top-of-iter-kt barrier -> no trailing barrier.
        load_stage(0, 0); CP_COMMIT();
        load_stage(1, 1); CP_COMMIT();
        for (int kt = 0; kt < nk; kt++) {
            if (kt + 1 < nk) { CP_WAIT1(); } else { CP_WAIT0(); }
            __syncthreads();
            compute_stage(sbase + (uint32_t)(kt % 3) * STG);
            if (kt + 2 < nk) { load_stage(kt + 2, (kt + 2) % 3); CP_COMMIT(); }
        }
    }

    if (MODE == 2) {
        __syncthreads();   // ensure stage reads done before smem reuse
        h16* st = reinterpret_cast<h16*>(smem);
        const int rr = wm0 + (lane >> 2);
        const int cc = wn0 + (lane & 3) * 2;
#pragma unroll
        for (int mt = 0; mt < 4; mt++) {
#pragma unroll
            for (int nt = 0; nt < 4; nt++) {
                const int r = rr + mt * 16;
                const int c = cc + nt * 8;
                st[r * 130 + c]           = __float2half_rn(acc[mt][nt][0]);
                st[r * 130 + c + 1]       = __float2half_rn(acc[mt][nt][1]);
                st[(r + 8) * 130 + c]     = __float2half_rn(acc[mt][nt][2]);
                st[(r + 8) * 130 + c + 1] = __float2half_rn(acc[mt][nt][3]);
            }
        }
        __syncthreads();
        const int d  = tid & 127;
        const int sh = tid >> 7;
        h16* dst = Cvt + (size_t)(n0 + d) * S + m0 + sh * 64;
#pragma unroll
        for (int i = 0; i < 64; i += 8) {
            __align__(16) h16 tmp[8];
#pragma unroll
            for (int u = 0; u < 8; u++) tmp[u] = st[(sh * 64 + i + u) * 130 + d];
            *reinterpret_cast<float4*>(dst + i) = *reinterpret_cast<float4*>(tmp);
        }
    } else {
        const int rbase = m0 + wm0 + (lane >> 2);
        const int cbase = n0 + wn0 + (lane & 3) * 2;
#pragma unroll
        for (int mt = 0; mt < 4; mt++) {
#pragma unroll
            for (int nt = 0; nt < 4; nt++) {
                const int row = rbase + mt * 16;
                const int col = cbase + nt * 8;
                float v0 = acc[mt][nt][0], v1 = acc[mt][nt][1];
                float v2 = acc[mt][nt][2], v3 = acc[mt][nt][3];
                if (MODE == 0) {
                    float2 c01 = __half22float2(*reinterpret_cast<__half2*>(&cacc[mt][nt][0]));
                    float2 c23 = __half22float2(*reinterpret_cast<__half2*>(&cacc[mt][nt][1]));
                    v0 += c01.x; v1 += c01.y; v2 += c23.x; v3 += c23.y;
                }
                *reinterpret_cast<float2*>(C + (size_t)row * ldc + col)       = make_float2(v0, v1);
                *reinterpret_cast<float2*>(C + (size_t)(row + 8) * ldc + col) = make_float2(v2, v3);
            }
        }
    }
}

// ---------------- flash attention: scores + softmax + PV fused ----------------
#define FL_STG   49152
#define FL_SMEM  (3 * FL_STG)
#define FL_KW_HI 0
#define FL_KW_LO 16384
#define FL_VT_HI 32768

__global__ void __launch_bounds__(256, 1)
flash_kernel(const h16* __restrict__ QWhi, const h16* __restrict__ QWlo,
             const h16* __restrict__ KWhi, const h16* __restrict__ KWlo,
             const h16* __restrict__ VThi,
             const float* __restrict__ AK,
             h16* __restrict__ AOhi)
{
    extern __shared__ char smem[];
    const uint32_t sbase = smem_u32(smem);
    const int tid = threadIdx.x, lane = tid & 31, wid = tid >> 5;
    const int m0 = blockIdx.x * 128;
    const int h  = blockIdx.y;

    const h16* Qh = QWhi + ((size_t)h * S + m0) * D;
    const h16* Ql = QWlo + ((size_t)h * S + m0) * D;
    const h16* Kh = KWhi + (size_t)h * S * D;
    const h16* Kl = KWlo + (size_t)h * S * D;
    const h16* Vh = VThi + (size_t)h * D * S;
    const float* ak = AK + (size_t)h * S;

#pragma unroll
    for (int j = 0; j < 8; j++) {
        int c = tid + j * 256;
        int k16 = c >> 8, row = (c & 255) >> 1, half = c & 1;
        uint32_t so = (uint32_t)(k16 * 4096 + row * 32 + ((half ^ ((row >> 2) & 1)) << 4));
        const size_t goff = (size_t)row * D + k16 * 16 + half * 8;
        cp16(sbase + so,         Qh + goff);
        cp16(sbase + 32768 + so, Ql + goff);
    }
    CP_COMMIT();
    CP_WAIT0();
    __syncthreads();

    uint32_t a_hi[8][4], a_lo[8][4];
    {
        const int arow = wid * 16 + (lane & 15);
        const uint32_t sw = (uint32_t)(((lane >> 4) ^ ((arow >> 2) & 1)) << 4);
#pragma unroll
        for (int kk = 0; kk < 8; kk++) {
            const uint32_t off = kk * 4096 + arow * 32 + sw;
            ldm_x4(a_hi[kk], sbase + off);
            ldm_x4(a_lo[kk], sbase + 32768 + off);
        }
    }
    __syncthreads();

    auto load_stage = [&](int kt, int stg) {
        const uint32_t sb = sbase + (uint32_t)stg * FL_STG;
        const int key0 = kt * 64;
#pragma unroll
        for (int j = 0; j < 4; j++) {
            int c = tid + j * 256;
            int k16 = c >> 7, row = (c & 127) >> 1, half = c & 1;
            uint32_t so = (uint32_t)(k16 * 2048 + row * 32 + ((half ^ ((row >> 2) & 1)) << 4));
            size_t goff = (size_t)(key0 + row) * D + k16 * 16 + half * 8;
            cp16(sb + FL_KW_HI + so, Kh + goff);
            cp16(sb + FL_KW_LO + so, Kl + goff);
        }
#pragma unroll
        for (int j = 0; j < 4; j++) {
            int c = tid + j * 256;
            int k16 = c >> 8, row = (c & 255) >> 1, half = c & 1;
            uint32_t so = (uint32_t)(k16 * 4096 + row * 32 + ((half ^ ((row >> 2) & 1)) << 4));
            size_t goff = (size_t)row * S + key0 + k16 * 16 + half * 8;
            cp16(sb + FL_VT_HI + so, Vh + goff);
        }
    };

    float acc_o[16][4];
#pragma unroll
    for (int i = 0; i < 16; i++)
#pragma unroll
        for (int r = 0; r < 4; r++) acc_o[i][r] = 0.f;
    float M0 = -1e30f, M1 = -1e30f, L0 = 0.f, L1 = 0.f;

    load_stage(0, 0); CP_COMMIT();
    load_stage(1, 1); CP_COMMIT();

    for (int kt = 0; kt < 32; kt++) {
        CP_WAIT1();
        __syncthreads();
        const uint32_t sb = sbase + (uint32_t)(kt % 3) * FL_STG;

        float sacc[8][4];
#pragma unroll
        for (int t = 0; t < 8; t++)
#pragma unroll
            for (int r = 0; r < 4; r++) sacc[t][r] = 0.f;
#pragma unroll
        for (int kk = 0; kk < 8; kk++) {
#pragma unroll
            for (int g = 0; g < 4; g++) {
                const int brow = g * 16 + (lane & 15);
                const uint32_t off = kk * 2048 + brow * 32
                                   + (((lane >> 4) ^ ((brow >> 2) & 1)) << 4);
                uint32_t bh[4], bl[4];
                ldm_x4(bh, sb + FL_KW_HI + off);
                ldm_x4(bl, sb + FL_KW_LO + off);
#pragma unroll
                for (int p = 0; p < 2; p++) {
                    const int t = g * 2 + p;
                    mma_f32acc(sacc[t], a_hi[kk], bh[p], bh[p + 2]);
                    mma_f32acc(sacc[t], a_hi[kk], bl[p], bl[p + 2]);
                    mma_f32acc(sacc[t], a_lo[kk], bh[p], bh[p + 2]);
                }
            }
        }
        const int keyc = kt * 64 + (lane & 3) * 2;
#pragma unroll
        for (int t = 0; t < 8; t++) {
            const float akA = __ldg(ak + keyc + t * 8);
            const float akB = __ldg(ak + keyc + t * 8 + 1);
            sacc[t][0] += akA; sacc[t][1] += akB;
            sacc[t][2] += akA; sacc[t][3] += akB;
        }
        float mt0 = -1e30f, mt1 = -1e30f;
#pragma unroll
        for (int t = 0; t < 8; t++) {
            mt0 = fmaxf(mt0, fmaxf(sacc[t][0], sacc[t][1]));
            mt1 = fmaxf(mt1, fmaxf(sacc[t][2], sacc[t][3]));
        }
        mt0 = fmaxf(mt0, __shfl_xor_sync(0xffffffffu, mt0, 1));
        mt0 = fmaxf(mt0, __shfl_xor_sync(0xffffffffu, mt0, 2));
        mt1 = fmaxf(mt1, __shfl_xor_sync(0xffffffffu, mt1, 1));
        mt1 = fmaxf(mt1, __shfl_xor_sync(0xffffffffu, mt1, 2));
        const float Mn0 = fmaxf(M0, mt0), Mn1 = fmaxf(M1, mt1);
        const float al0 = __expf(M0 - Mn0), al1 = __expf(M1 - Mn1);
        M0 = Mn0; M1 = Mn1;

        uint32_t pa[4][4];
        float s0 = 0.f, s1 = 0.f;
#pragma unroll
        for (int q = 0; q < 4; q++) {
#pragma unroll
            for (int pp = 0; pp < 2; pp++) {
                const int t = q * 2 + pp;
                const float p00 = __expf(sacc[t][0] - Mn0);
                const float p01 = __expf(sacc[t][1] - Mn0);
                const float p10 = __expf(sacc[t][2] - Mn1);
                const float p11 = __expf(sacc[t][3] - Mn1);
                s0 += p00 + p01; s1 += p10 + p11;
                pa[q][pp * 2]     = h2pack(p00, p01);
                pa[q][pp * 2 + 1] = h2pack(p10, p11);
            }
        }
        L0 = L0 * al0 + s0; L1 = L1 * al1 + s1;
#pragma unroll
        for (int nt = 0; nt < 16; nt++) {
            acc_o[nt][0] *= al0; acc_o[nt][1] *= al0;
            acc_o[nt][2] *= al1; acc_o[nt][3] *= al1;
        }
#pragma unroll
        for (int q = 0; q < 4; q++) {
#pragma unroll
            for (int dg = 0; dg < 8; dg++) {
                const int vrow = dg * 16 + (lane & 15);
                const uint32_t off = q * 4096 + vrow * 32
                                   + (((lane >> 4) ^ ((vrow >> 2) & 1)) << 4);
                uint32_t vh[4];
                ldm_x4(vh, sb + FL_VT_HI + off);
#pragma unroll
                for (int p = 0; p < 2; p++) {
                    const int nt = dg * 2 + p;
                    mma_f32acc(acc_o[nt], pa[q], vh[p], vh[p + 2]);
                }
            }
        }
        if (kt + 2 < 32) load_stage(kt + 2, (kt + 2) % 3);
        CP_COMMIT();
    }

    L0 += __shfl_xor_sync(0xffffffffu, L0, 1);
    L0 += __shfl_xor_sync(0xffffffffu, L0, 2);
    L1 += __shfl_xor_sync(0xffffffffu, L1, 1);
    L1 += __shfl_xor_sync(0xffffffffu, L1, 2);
    const float i0 = 1.f / L0, i1 = 1.f / L1;
    const int r0 = m0 + wid * 16 + (lane >> 2);
    const int cb = (lane & 3) * 2;
#pragma unroll
    for (int nt = 0; nt < 16; nt++) {
        const int d = nt * 8 + cb;
        __half2 hp0 = __floats2half2_rn(acc_o[nt][0] * i0, acc_o[nt][1] * i0);
        __half2 hp1 = __floats2half2_rn(acc_o[nt][2] * i1, acc_o[nt][3] * i1);
        *reinterpret_cast<__half2*>(AOhi + (size_t)r0 * H + h * D + d)       = hp0;
        *reinterpret_cast<__half2*>(AOhi + (size_t)(r0 + 8) * H + h * D + d) = hp1;
    }
}

// ---------------- unified prep: all splits + casts in one launch --------------
#define PREP_UNITS 1835008
__global__ void prep_kernel(const float* __restrict__ X,
                            const float* __restrict__ wq, const float* __restrict__ wk,
                            const float* __restrict__ wv, const float* __restrict__ wo,
                            h16* __restrict__ Xhi, h16* __restrict__ Xlo,
                            h16* __restrict__ wqhi, h16* __restrict__ wqlo,
                            h16* __restrict__ wkhi, h16* __restrict__ wklo,
                            h16* __restrict__ wvhi, h16* __restrict__ wohi)
{
    int i = blockIdx.x * blockDim.x + threadIdx.x;
    if (i >= PREP_UNITS) return;
    const float* src;
    h16 *hi, *lo = nullptr;
    int j;
    if (i < 262144)       { src = X;  hi = Xhi;  lo = Xlo;  j = i; }
    else if (i < 786432)  { src = wq; hi = wqhi; lo = wqlo; j = i - 262144; }
    else if (i < 1310720) { src = wk; hi = wkhi; lo = wklo; j = i - 786432; }
    else if (i < 1572864) { src = wv; hi = wvhi;            j = i - 1310720; }
    else                  { src = wo; hi = wohi;            j = i - 1572864; }

    const float4* xp = reinterpret_cast<const float4*>(src) + (size_t)j * 4;
    float4 v0 = xp[0], v1 = xp[1], v2 = xp[2], v3 = xp[3];
    float vv[16] = {v0.x, v0.y, v0.z, v0.w, v1.x, v1.y, v1.z, v1.w,
                    v2.x, v2.y, v2.z, v2.w, v3.x, v3.y, v3.z, v3.w};
    __align__(16) h16 hb[16];
    if (lo != nullptr) {
        __align__(16) h16 lb[16];
#pragma unroll
        for (int u = 0; u < 16; u++) split2h(vv[u], hb[u], lb[u]);
        float4* lp = reinterpret_cast<float4*>(lo) + (size_t)j * 2;
        lp[0] = *reinterpret_cast<float4*>(lb);
        lp[1] = *reinterpret_cast<float4*>(lb + 8);
    } else {
#pragma unroll
        for (int u = 0; u < 16; u++) hb[u] = __float2half_rn(vv[u]);
    }
    float4* hp = reinterpret_cast<float4*>(hi) + (size_t)j * 2;
    hp[0] = *reinterpret_cast<float4*>(hb);
    hp[1] = *reinterpret_cast<float4*>(hb + 8);
}

// ---------------- softplus + var-weight + RoPE (fast-math) -------------------
__global__ void __launch_bounds__(256)
transform_kernel(const float* __restrict__ QKraw,
                 const float* __restrict__ cosT, const float* __restrict__ sinT,
                 h16* __restrict__ QWhi, h16* __restrict__ QWlo,
                 h16* __restrict__ KWhi, h16* __restrict__ KWlo,
                 float* __restrict__ AK)
{
    const int item = blockIdx.x * 8 + (threadIdx.x >> 5);
    const int lane = threadIdx.x & 31;
    const int s = item & (S - 1);
    const int h = (item >> 11) & (NH - 1);
    const int z = item >> 15;
    h16* Whi = z ? KWhi : QWhi;
    h16* Wlo = z ? KWlo : QWlo;

    const float* base = QKraw + (size_t)s * (4 * H) + z * (2 * H) + h * (2 * D);
    float w[4], sg[4];
#pragma unroll
    for (int j = 0; j < 4; j++) {
        const int d = lane + 32 * j;
        const float mu = base[d];
        const float sr = base[D + d];
        const float sp = (sr > 8.f) ? sr : __logf(1.f + __expf(sr));
        sg[j] = sp + 1e-4f;
        w[j] = mu * rsqrtf(sg[j]);
    }
    float wr[4];
#pragma unroll
    for (int j = 0; j < 4; j++) {
        const int d = lane + 32 * j;
        const float rh = (j < 2) ? -w[j + 2] : w[j - 2];
        wr[j] = w[j] * cosT[(size_t)s * D + d] + rh * sinT[(size_t)s * D + d];
        h16 hh, ll;
        split2h(wr[j], hh, ll);
        const size_t o = ((size_t)h * S + s) * D + d;
        Whi[o] = hh;  Wlo[o] = ll;
    }
    if (z) {
        float red = 0.f;
#pragma unroll
        for (int j = 0; j < 4; j++) red += wr[j] * wr[j] + __logf(sg[j]);
#pragma unroll
        for (int o = 16; o > 0; o >>= 1) red += __shfl_xor_sync(0xffffffffu, red, o);
        if (lane == 0) AK[(size_t)h * S + s] = -0.5f * red;
    }
}

// ---------------- launch ------------------------------------------------------
extern "C" void kernel_launch(void* const* d_in, const int* in_sizes, int n_in,
                              void* d_out, int out_size)
{
    const float* X    = (const float*)d_in[0];
    const float* cosT = (const float*)d_in[1];
    const float* sinT = (const float*)d_in[2];
    const float* w_q  = (const float*)d_in[3];
    const float* w_k  = (const float*)d_in[4];
    const float* w_v  = (const float*)d_in[5];
    const float* w_o  = (const float*)d_in[6];
    float* out = (float*)d_out;

    h16 *Xhi, *Xlo, *wqhi, *wqlo, *wkhi, *wklo, *wvhi, *wohi;
    float *QKraw, *AK;
    h16 *QWhi, *QWlo, *KWhi, *KWlo, *VThi, *AOhi;
    cudaGetSymbolAddress((void**)&Xhi, g_Xhi);   cudaGetSymbolAddress((void**)&Xlo, g_Xlo);
    cudaGetSymbolAddress((void**)&wqhi, g_wqhi); cudaGetSymbolAddress((void**)&wqlo, g_wqlo);
    cudaGetSymbolAddress((void**)&wkhi, g_wkhi); cudaGetSymbolAddress((void**)&wklo, g_wklo);
    cudaGetSymbolAddress((void**)&wvhi, g_wvhi); cudaGetSymbolAddress((void**)&wohi, g_wohi);
    cudaGetSymbolAddress((void**)&QKraw, g_QKraw);
    cudaGetSymbolAddress((void**)&QWhi, g_QWhi); cudaGetSymbolAddress((void**)&QWlo, g_QWlo);
    cudaGetSymbolAddress((void**)&KWhi, g_KWhi); cudaGetSymbolAddress((void**)&KWlo, g_KWlo);
    cudaGetSymbolAddress((void**)&AK, g_AK);
    cudaGetSymbolAddress((void**)&VThi, g_VThi);
    cudaGetSymbolAddress((void**)&AOhi, g_AOhi);

    cudaFuncSetAttribute(gemm_kernel<0>,
                         cudaFuncAttributeMaxDynamicSharedMemorySize, GEMM_SMEM0);
    cudaFuncSetAttribute(gemm_kernel<1>,
                         cudaFuncAttributeMaxDynamicSharedMemorySize, GEMM_SMEM12);
    cudaFuncSetAttribute(gemm_kernel<2>,
                         cudaFuncAttributeMaxDynamicSharedMemorySize, GEMM_SMEM12);
    cudaFuncSetAttribute(flash_kernel,
                         cudaFuncAttributeMaxDynamicSharedMemorySize, FL_SMEM);

    prep_kernel<<<(PREP_UNITS + 255) / 256, 256>>>(
        X, w_q, w_k, w_v, w_o,
        Xhi, Xlo, wqhi, wqlo, wkhi, wklo, wvhi, wohi);

    gemm_kernel<0><<<dim3(8192 / 128, S / 128, 1), 256, GEMM_SMEM0>>>(
        S, 8192, H, Xhi, Xlo, H, wqhi, wqlo, H,
        wkhi, wklo, 4096, QKraw, 8192, nullptr);

    gemm_kernel<2><<<dim3(H / 128, S / 128, 1), 256, GEMM_SMEM12>>>(
        S, H, H, Xhi, nullptr, H, wvhi, nullptr, H,
        nullptr, nullptr, 1 << 30, nullptr, 0, VThi);

    transform_kernel<<<(S * NH * 2) / 8, 256>>>(QKraw, cosT, sinT,
                                                QWhi, QWlo, KWhi, KWlo, AK);

    flash_kernel<<<dim3(S / 128, NH), 256, FL_SMEM>>>(
        QWhi, QWlo, KWhi, KWlo, VThi, AK, AOhi);

    gemm_kernel<1><<<dim3(H / 128, S / 128, 1), 256, GEMM_SMEM12>>>(
        S, H, H, AOhi, nullptr, H, wohi, nullptr, H,
        nullptr, nullptr, 1 << 30, out, H, nullptr);
}